// round 11
// baseline (speedup 1.0000x reference)
#include <cuda_runtime.h>

// QAttentionLayer: out[..., i] = cumprod_{j<=i}( cos(x_j) * cos(w_j) )
// x: [16384, 256, 10] fp32. Rows of 10 floats; lcm(10,4)=20 -> 5-lane groups,
// each lane owns ONE contiguous float4 (perfect coalescing), cross-lane prefix
// product via 2 SHFL.IDX. ILP=8: 8 front-batched LDG.128 per warp-tile.
// Warp-level grid-stride over tiles with the flat R8 body unchanged:
// grid = 148*5 CTAs exactly (one resident wave) -> no wave-transition cost,
// no tail-wave imbalance. No cross-iteration buffering (R7's mistake).

#define NQ  10
#define ILP 8
#define GPT (6 * ILP)   // groups per warp-tile = 48

__global__ __launch_bounds__(256, 5)
void qattn_main(const float4* __restrict__ x4,
                float4* __restrict__ o4,
                const float* __restrict__ w,
                int n_groups, int n_tiles, int warp_stride)
{
    int tid  = blockIdx.x * blockDim.x + threadIdx.x;
    int warp = tid >> 5;
    int lane = tid & 31;
    int gw   = lane / 5;          // group slot within warp tile: 0..6 (6 => idle)
    int k    = lane - gw * 5;     // float4 slot within group: 0..4
    int base = lane - k;          // first lane of this 5-lane group
    bool lane_ok = (gw < 6);

    // Weight cosines for positions p = 4k..4k+3 (q = p mod 10), computed once.
    float cw0, cw1, cw2, cw3;
    {
        int p = 4 * k;
        int q0 = (p     < NQ) ? p     : p - NQ;
        int q1 = (p + 1 < NQ) ? p + 1 : p + 1 - NQ;
        int q2 = (p + 2 < NQ) ? p + 2 : p + 2 - NQ;
        int q3 = (p + 3 < NQ) ? p + 3 : p + 3 - NQ;
        cw0 = __cosf(__ldg(&w[q0]));
        cw1 = __cosf(__ldg(&w[q1]));
        cw2 = __cosf(__ldg(&w[q2]));
        cw3 = __cosf(__ldg(&w[q3]));
    }

    bool r2 = (k == 2);                          // in-thread row boundary lane
    int srcA = base + ((k >= 3) ? 2 : 0);
    int srcB = base + ((k == 4) ? 3 : 1);

    for (int t = warp; t < n_tiles; t += warp_stride) {
        int g0    = t * GPT + gw;                // first group of this lane
        int base4 = g0 * 5 + k;                  // its float4 index

        float4 a[ILP];
        // Front-batch ALL loads: MLP = ILP. Predicated, single path.
#pragma unroll
        for (int it = 0; it < ILP; it++) {
            bool act = lane_ok && (g0 + it * 6 < n_groups);
            a[it] = act ? __ldcs(&x4[base4 + it * 30])
                        : make_float4(0.f, 0.f, 0.f, 0.f);
        }

#pragma unroll
        for (int it = 0; it < ILP; it++) {
            float c0 = __cosf(a[it].x) * cw0;
            float c1 = __cosf(a[it].y) * cw1;
            float c2 = __cosf(a[it].z) * cw2;
            float c3 = __cosf(a[it].w) * cw3;

            // Local segmented inclusive scan (reset at p=10 -> k==2, j==2)
            float lp0 = c0;
            float lp1 = lp0 * c1;
            float lp2 = r2 ? c2 : lp1 * c2;
            float lp3 = lp2 * c3;

            // Cross-lane exclusive prefix (2 IDX shuffles)
            float sA = __shfl_sync(0xffffffffu, lp3, srcA);
            float sB = __shfl_sync(0xffffffffu, lp3, srcB);
            float pre = (k == 0) ? 1.0f
                      : (k == 1 || k == 3) ? sA
                      : sA * sB;
            float pre_hi = r2 ? 1.0f : pre;

            float4 r;
            r.x = lp0 * pre;
            r.y = lp1 * pre;
            r.z = lp2 * pre_hi;
            r.w = lp3 * pre_hi;

            bool act = lane_ok && (g0 + it * 6 < n_groups);
            if (act) __stcs(&o4[base4 + it * 30], r);
        }
    }
}

extern "C" void kernel_launch(void* const* d_in, const int* in_sizes, int n_in,
                              void* d_out, int out_size)
{
    const float* x = (const float*)d_in[0];   // [16384*256*10] fp32
    const float* w = (const float*)d_in[1];   // [10] fp32
    float* out = (float*)d_out;

    long long total = (long long)in_sizes[0];   // 41,943,040 floats
    int n_groups    = (int)(total / 20);        // 2,097,152 groups of 20 floats
    int n_tiles     = (n_groups + GPT - 1) / GPT;  // 43,691 warp-tiles

    int block = 256;
    int grid  = 148 * 5;                        // one full resident wave
    int warp_stride = grid * (block / 32);      // 5920 warps

    qattn_main<<<grid, block>>>(reinterpret_cast<const float4*>(x),
                                reinterpret_cast<float4*>(out),
                                w, n_groups, n_tiles, warp_stride);
}

// round 12
// speedup vs baseline: 1.1144x; 1.1144x over previous
#include <cuda_runtime.h>

// QAttentionLayer: out[..., i] = cumprod_{j<=i}( cos(x_j) * cos(w_j) )
// x: [16384, 256, 10] fp32. Rows of 10 floats; lcm(10,4)=20 -> 5-lane groups,
// each lane owns ONE contiguous float4 (perfect coalescing), cross-lane prefix
// product via 2 SHFL.IDX. ILP=8: 8 front-batched LDG.128 per thread (MLP_p1=8).
// Single uniform predicated path, one tile per warp, launch-per-tile (the CTA
// work distributor pipelines replacement; all loop/persistence variants lose).
// launch_bounds(256,5) -> 48 regs, 5 CTAs/SM.
//
// CONVERGED: 335.5MB @ 46.2us = 7.26 TB/s (~91% of HBM spec, at the B300
// path-independent LTS cap). Measured losers: control-flow tail peel (R5,
// +5.8us), persistent double-buffer (R7, +5.8us), 256-bit v8 ops (R9, +1.6us),
// warp grid-stride with identical body (R11, +6.1us).

#define NQ  10
#define ILP 8

__global__ __launch_bounds__(256, 5)
void qattn_main(const float4* __restrict__ x4,
                float4* __restrict__ o4,
                const float* __restrict__ w,
                int n_groups)
{
    int tid  = blockIdx.x * blockDim.x + threadIdx.x;
    int warp = tid >> 5;
    int lane = tid & 31;
    int gw   = lane / 5;          // group slot within warp tile: 0..6 (6 => idle)
    int k    = lane - gw * 5;     // float4 slot within group: 0..4
    int base = lane - k;          // first lane of this 5-lane group
    bool lane_ok = (gw < 6);

    // Weight cosines for positions p = 4k..4k+3 (q = p mod 10), computed once.
    float cw0, cw1, cw2, cw3;
    {
        int p = 4 * k;
        int q0 = (p     < NQ) ? p     : p - NQ;
        int q1 = (p + 1 < NQ) ? p + 1 : p + 1 - NQ;
        int q2 = (p + 2 < NQ) ? p + 2 : p + 2 - NQ;
        int q3 = (p + 3 < NQ) ? p + 3 : p + 3 - NQ;
        cw0 = __cosf(__ldg(&w[q0]));
        cw1 = __cosf(__ldg(&w[q1]));
        cw2 = __cosf(__ldg(&w[q2]));
        cw3 = __cosf(__ldg(&w[q3]));
    }

    bool r2 = (k == 2);                          // in-thread row boundary lane
    int srcA = base + ((k >= 3) ? 2 : 0);
    int srcB = base + ((k == 4) ? 3 : 1);

    int g0    = warp * (6 * ILP) + gw;           // first group of this lane
    int base4 = g0 * 5 + k;                      // its float4 index

    float4 a[ILP];
    // Front-batch ALL loads: MLP = ILP. Predicated, single path.
#pragma unroll
    for (int it = 0; it < ILP; it++) {
        bool act = lane_ok && (g0 + it * 6 < n_groups);
        a[it] = act ? __ldcs(&x4[base4 + it * 30])
                    : make_float4(0.f, 0.f, 0.f, 0.f);
    }

#pragma unroll
    for (int it = 0; it < ILP; it++) {
        float c0 = __cosf(a[it].x) * cw0;
        float c1 = __cosf(a[it].y) * cw1;
        float c2 = __cosf(a[it].z) * cw2;
        float c3 = __cosf(a[it].w) * cw3;

        // Local segmented inclusive scan (reset at p=10 -> k==2, j==2)
        float lp0 = c0;
        float lp1 = lp0 * c1;
        float lp2 = r2 ? c2 : lp1 * c2;
        float lp3 = lp2 * c3;

        // Cross-lane exclusive prefix (2 IDX shuffles)
        float sA = __shfl_sync(0xffffffffu, lp3, srcA);
        float sB = __shfl_sync(0xffffffffu, lp3, srcB);
        float pre = (k == 0) ? 1.0f
                  : (k == 1 || k == 3) ? sA
                  : sA * sB;
        float pre_hi = r2 ? 1.0f : pre;

        float4 r;
        r.x = lp0 * pre;
        r.y = lp1 * pre;
        r.z = lp2 * pre_hi;
        r.w = lp3 * pre_hi;

        bool act = lane_ok && (g0 + it * 6 < n_groups);
        if (act) __stcs(&o4[base4 + it * 30], r);
    }
}

extern "C" void kernel_launch(void* const* d_in, const int* in_sizes, int n_in,
                              void* d_out, int out_size)
{
    const float* x = (const float*)d_in[0];   // [16384*256*10] fp32
    const float* w = (const float*)d_in[1];   // [10] fp32
    float* out = (float*)d_out;

    long long total = (long long)in_sizes[0];   // 41,943,040 floats
    int n_groups    = (int)(total / 20);        // 2,097,152 groups of 20 floats
    long long warps = ((long long)n_groups + 6 * ILP - 1) / (6 * ILP);
    long long threads = warps * 32;
    int block = 256;
    long long grid = (threads + block - 1) / block;

    qattn_main<<<(unsigned)grid, block>>>(reinterpret_cast<const float4*>(x),
                                          reinterpret_cast<float4*>(out),
                                          w, n_groups);
}

// round 13
// speedup vs baseline: 1.1210x; 1.0060x over previous
#include <cuda_runtime.h>

// QAttentionLayer: out[..., i] = cumprod_{j<=i}( cos(x_j) * cos(w_j) )
// x: [16384, 256, 10] fp32. Rows of 10 floats; lcm(10,4)=20 -> 5-lane groups,
// each lane owns ONE contiguous float4 (perfect coalescing), cross-lane prefix
// product via 2 SHFL.IDX. ILP=10: 10 front-batched LDG.128 per thread
// (MLP_p1=10, +25% bytes in flight vs ILP=8). Single uniform predicated path,
// one tile per warp, launch-per-tile. launch_bounds(256,4) -> 64-reg cap
// (need ~58, no spill), 4 CTAs/SM.
//
// Probe: if this is not faster than the 3x-reproduced ILP=8 optimum
// (53.73us, 7.26 TB/s ~ 91% HBM spec), the ILP curve is flat past 8 and
// the R12 kernel is final.

#define NQ  10
#define ILP 10

__global__ __launch_bounds__(256, 4)
void qattn_main(const float4* __restrict__ x4,
                float4* __restrict__ o4,
                const float* __restrict__ w,
                int n_groups)
{
    int tid  = blockIdx.x * blockDim.x + threadIdx.x;
    int warp = tid >> 5;
    int lane = tid & 31;
    int gw   = lane / 5;          // group slot within warp tile: 0..6 (6 => idle)
    int k    = lane - gw * 5;     // float4 slot within group: 0..4
    int base = lane - k;          // first lane of this 5-lane group
    bool lane_ok = (gw < 6);

    // Weight cosines for positions p = 4k..4k+3 (q = p mod 10), computed once.
    float cw0, cw1, cw2, cw3;
    {
        int p = 4 * k;
        int q0 = (p     < NQ) ? p     : p - NQ;
        int q1 = (p + 1 < NQ) ? p + 1 : p + 1 - NQ;
        int q2 = (p + 2 < NQ) ? p + 2 : p + 2 - NQ;
        int q3 = (p + 3 < NQ) ? p + 3 : p + 3 - NQ;
        cw0 = __cosf(__ldg(&w[q0]));
        cw1 = __cosf(__ldg(&w[q1]));
        cw2 = __cosf(__ldg(&w[q2]));
        cw3 = __cosf(__ldg(&w[q3]));
    }

    bool r2 = (k == 2);                          // in-thread row boundary lane
    int srcA = base + ((k >= 3) ? 2 : 0);
    int srcB = base + ((k == 4) ? 3 : 1);

    int g0    = warp * (6 * ILP) + gw;           // first group of this lane
    int base4 = g0 * 5 + k;                      // its float4 index

    float4 a[ILP];
    // Front-batch ALL loads: MLP = ILP. Predicated, single path.
#pragma unroll
    for (int it = 0; it < ILP; it++) {
        bool act = lane_ok && (g0 + it * 6 < n_groups);
        a[it] = act ? __ldcs(&x4[base4 + it * 30])
                    : make_float4(0.f, 0.f, 0.f, 0.f);
    }

#pragma unroll
    for (int it = 0; it < ILP; it++) {
        float c0 = __cosf(a[it].x) * cw0;
        float c1 = __cosf(a[it].y) * cw1;
        float c2 = __cosf(a[it].z) * cw2;
        float c3 = __cosf(a[it].w) * cw3;

        // Local segmented inclusive scan (reset at p=10 -> k==2, j==2)
        float lp0 = c0;
        float lp1 = lp0 * c1;
        float lp2 = r2 ? c2 : lp1 * c2;
        float lp3 = lp2 * c3;

        // Cross-lane exclusive prefix (2 IDX shuffles)
        float sA = __shfl_sync(0xffffffffu, lp3, srcA);
        float sB = __shfl_sync(0xffffffffu, lp3, srcB);
        float pre = (k == 0) ? 1.0f
                  : (k == 1 || k == 3) ? sA
                  : sA * sB;
        float pre_hi = r2 ? 1.0f : pre;

        float4 r;
        r.x = lp0 * pre;
        r.y = lp1 * pre;
        r.z = lp2 * pre_hi;
        r.w = lp3 * pre_hi;

        bool act = lane_ok && (g0 + it * 6 < n_groups);
        if (act) __stcs(&o4[base4 + it * 30], r);
    }
}

extern "C" void kernel_launch(void* const* d_in, const int* in_sizes, int n_in,
                              void* d_out, int out_size)
{
    const float* x = (const float*)d_in[0];   // [16384*256*10] fp32
    const float* w = (const float*)d_in[1];   // [10] fp32
    float* out = (float*)d_out;

    long long total = (long long)in_sizes[0];   // 41,943,040 floats
    int n_groups    = (int)(total / 20);        // 2,097,152 groups of 20 floats
    long long warps = ((long long)n_groups + 6 * ILP - 1) / (6 * ILP);
    long long threads = warps * 32;
    int block = 256;
    long long grid = (threads + block - 1) / block;

    qattn_main<<<(unsigned)grid, block>>>(reinterpret_cast<const float4*>(x),
                                          reinterpret_cast<float4*>(out),
                                          w, n_groups);
}